// round 5
// baseline (speedup 1.0000x reference)
#include <cuda_runtime.h>
#include <cuda_bf16.h>
#include <cstdint>
#include <cstddef>

// Problem constants (fixed by the reference)
#define NN 100000
#define HH 512
#define EE 160000
#define BN_EPS 1e-5f
#define SLOPE 0.01f

// ---------------- scratch (no cudaMalloc allowed) ----------------
__device__ float g_A[(size_t)NN * HH];
__device__ float g_B[(size_t)NN * HH];
__device__ float g_C[(size_t)NN * HH];
__device__ float g_dinv[NN];
__device__ int   g_deg[NN];
__device__ float g_colsum[HH];
__device__ float g_colsq[HH];
__device__ float g_scale[HH];
__device__ float g_shift[HH];
__device__ float g_weff[HH + 1];
__device__ int   g_is64;

// transposed + hi/lo-split weights: T[n][k] = bf16(W[k][n]), residual in l
__device__ __nv_bfloat16 g_w1h[HH * HH];
__device__ __nv_bfloat16 g_w1l[HH * HH];
__device__ __nv_bfloat16 g_wch[HH * HH];
__device__ __nv_bfloat16 g_wcl[HH * HH];

// ---------------- setup kernels ----------------
__global__ void k_prep(const int* __restrict__ ei) {
    int i = blockIdx.x * blockDim.x + threadIdx.x;
    if (i == 0)
        g_is64 = ((ei[1] | ei[3] | ei[5] | ei[7] | ei[9]) == 0) ? 1 : 0;
    if (i < NN) g_deg[i] = 0;
}

__global__ void k_deg(const int* __restrict__ ei) {
    int e = blockIdx.x * blockDim.x + threadIdx.x;
    if (e >= EE) return;
    int is64 = g_is64;
    int dst = is64 ? ei[2 * EE + 2 * e] : ei[EE + e];
    atomicAdd(&g_deg[dst], 1);
}

__global__ void k_dinv() {
    int i = blockIdx.x * blockDim.x + threadIdx.x;
    if (i < NN) g_dinv[i] = rsqrtf((float)g_deg[i] + 1.0f);
}

__global__ void k_conv_w(const float* __restrict__ W, __nv_bfloat16* __restrict__ Th,
                         __nv_bfloat16* __restrict__ Tl) {
    int k = blockIdx.x;
    for (int n = threadIdx.x; n < HH; n += blockDim.x) {
        float f = W[(size_t)k * HH + n];
        __nv_bfloat16 h = __float2bfloat16(f);
        float r = f - __bfloat162float(h);
        Th[(size_t)n * HH + k] = h;
        Tl[(size_t)n * HH + k] = __float2bfloat16(r);
    }
}

// ---------------- tensor-core GEMM via mma.sync -----------------------------
// C[NN,512] = f(A)[NN,512] @ W[512,512]; optional fused BN+LReLU on A-load,
// optional fused agg-init epilogue (C2 = dinv^2 * C + bc).
#define BM 128
#define BNT 128
#define BK 32
#define NCHUNK (HH / BK)     // 16
#define PADK 40

__device__ __forceinline__ void ldsm_x4(uint32_t* r, uint32_t addr) {
    asm volatile("ldmatrix.sync.aligned.m8n8.x4.shared.b16 {%0,%1,%2,%3}, [%4];"
                 : "=r"(r[0]), "=r"(r[1]), "=r"(r[2]), "=r"(r[3]) : "r"(addr));
}
__device__ __forceinline__ void mma_bf16(float* d, const uint32_t* a,
                                         const uint32_t* b) {
    asm volatile(
        "mma.sync.aligned.m16n8k16.row.col.f32.bf16.bf16.f32 "
        "{%0,%1,%2,%3}, {%4,%5,%6,%7}, {%8,%9}, {%0,%1,%2,%3};"
        : "+f"(d[0]), "+f"(d[1]), "+f"(d[2]), "+f"(d[3])
        : "r"(a[0]), "r"(a[1]), "r"(a[2]), "r"(a[3]), "r"(b[0]), "r"(b[1]));
}
__device__ __forceinline__ uint32_t smem_u32(const void* p) {
    uint32_t a;
    asm("{ .reg .u64 t; cvta.to.shared.u64 t, %1; cvt.u32.u64 %0, t; }"
        : "=r"(a) : "l"(p));
    return a;
}
__device__ __forceinline__ uint32_t packbf(float x, float y) {
    __nv_bfloat162 t = __floats2bfloat162_rn(x, y);
    return *(uint32_t*)&t;
}
__device__ __forceinline__ float lrelu1(float x) {
    return x >= 0.f ? x : SLOPE * x;
}
__device__ __forceinline__ float4 xform(float4 v, int col,
                                        const float* __restrict__ scale,
                                        const float* __restrict__ shift) {
    float4 s = __ldg((const float4*)(scale + col));
    float4 t = __ldg((const float4*)(shift + col));
    v.x = lrelu1(fmaf(s.x, v.x, t.x));
    v.y = lrelu1(fmaf(s.y, v.y, t.y));
    v.z = lrelu1(fmaf(s.z, v.z, t.z));
    v.w = lrelu1(fmaf(s.w, v.w, t.w));
    return v;
}

__global__ __launch_bounds__(256)
void k_gemm_mma(const float* __restrict__ A,
                const __nv_bfloat16* __restrict__ Wh,
                const __nv_bfloat16* __restrict__ Wl,
                const float* __restrict__ bias,    // add to C (may be null)
                const float* __restrict__ scale,   // fused BN on A (may be null)
                const float* __restrict__ shift,
                float* __restrict__ C,
                float* __restrict__ C2,            // agg-init out (may be null)
                const float* __restrict__ bc) {    // bias for C2
    __shared__ __align__(16) __nv_bfloat16 sAh[BM * PADK];
    __shared__ __align__(16) __nv_bfloat16 sAl[BM * PADK];
    __shared__ __align__(16) __nv_bfloat16 sBh[BNT * PADK];
    __shared__ __align__(16) __nv_bfloat16 sBl[BNT * PADK];

    const int tid = threadIdx.x;
    const int wid = tid >> 5;
    const int lane = tid & 31;
    // n-fastest swizzle: 4 n-tiles of the same m-rows are adjacent -> A L2 reuse
    const int bm = (blockIdx.x >> 2) * BM;
    const int bn = (blockIdx.x & 3) * BNT;
    const int wm = (wid & 1) * 64;
    const int wn = (wid >> 1) * 32;

    const uint32_t uAh = smem_u32(sAh), uAl = smem_u32(sAl);
    const uint32_t uBh = smem_u32(sBh), uBl = smem_u32(sBl);

    float acc[4][4][4];
#pragma unroll
    for (int i = 0; i < 4; i++)
#pragma unroll
        for (int j = 0; j < 4; j++)
#pragma unroll
            for (int f = 0; f < 4; f++) acc[i][j][f] = 0.f;

    float4 fa[4];
    uint4 pwh[2], pwl[2];

    // ---- load chunk 0 ----
#pragma unroll
    for (int j = 0; j < 4; j++) {
        int lin = tid + j * 256;
        int r = lin >> 3, kc = (lin & 7) << 2;
        int grow = bm + r;
        float4 v = (grow < NN) ? *(const float4*)(A + (size_t)grow * HH + kc)
                               : make_float4(0.f, 0.f, 0.f, 0.f);
        if (scale) v = xform(v, kc, scale, shift);
        fa[j] = v;
    }
#pragma unroll
    for (int j = 0; j < 2; j++) {
        int lin = tid + j * 256;
        int r = lin >> 2, c8 = (lin & 3) << 3;
        size_t g = (size_t)(bn + r) * HH + c8;
        pwh[j] = *(const uint4*)(Wh + g);
        pwl[j] = *(const uint4*)(Wl + g);
    }

    for (int s = 0; s < NCHUNK; s++) {
#pragma unroll
        for (int j = 0; j < 4; j++) {
            int lin = tid + j * 256;
            int r = lin >> 3, kc = (lin & 7) << 2;
            float4 v = fa[j];
            __nv_bfloat16 h0 = __float2bfloat16(v.x), h1 = __float2bfloat16(v.y);
            __nv_bfloat16 h2 = __float2bfloat16(v.z), h3 = __float2bfloat16(v.w);
            uint2 hp, lp;
            hp.x = ((uint32_t)__bfloat16_as_ushort(h0)) |
                   ((uint32_t)__bfloat16_as_ushort(h1) << 16);
            hp.y = ((uint32_t)__bfloat16_as_ushort(h2)) |
                   ((uint32_t)__bfloat16_as_ushort(h3) << 16);
            lp.x = packbf(v.x - __bfloat162float(h0), v.y - __bfloat162float(h1));
            lp.y = packbf(v.z - __bfloat162float(h2), v.w - __bfloat162float(h3));
            *(uint2*)(sAh + r * PADK + kc) = hp;
            *(uint2*)(sAl + r * PADK + kc) = lp;
        }
#pragma unroll
        for (int j = 0; j < 2; j++) {
            int lin = tid + j * 256;
            int r = lin >> 2, c8 = (lin & 3) << 3;
            *(uint4*)(sBh + r * PADK + c8) = pwh[j];
            *(uint4*)(sBl + r * PADK + c8) = pwl[j];
        }
        __syncthreads();

        if (s + 1 < NCHUNK) {
            int k0n = (s + 1) * BK;
#pragma unroll
            for (int j = 0; j < 4; j++) {
                int lin = tid + j * 256;
                int r = lin >> 3, kc = (lin & 7) << 2;
                int grow = bm + r;
                float4 v = (grow < NN)
                               ? *(const float4*)(A + (size_t)grow * HH + k0n + kc)
                               : make_float4(0.f, 0.f, 0.f, 0.f);
                if (scale) v = xform(v, k0n + kc, scale, shift);
                fa[j] = v;
            }
#pragma unroll
            for (int j = 0; j < 2; j++) {
                int lin = tid + j * 256;
                int r = lin >> 2, c8 = (lin & 3) << 3;
                size_t g = (size_t)(bn + r) * HH + k0n + c8;
                pwh[j] = *(const uint4*)(Wh + g);
                pwl[j] = *(const uint4*)(Wl + g);
            }
        }

#pragma unroll
        for (int ks = 0; ks < 2; ks++) {
            const int k0 = ks * 16;
            const uint32_t lrow = (lane & 15);
            const uint32_t lk = (lane >> 4) * 8;

            uint32_t bh[4][2], bl[4][2];
#pragma unroll
            for (int p = 0; p < 2; p++) {
                uint32_t off = ((wn + p * 16 + lrow) * PADK + k0 + lk) * 2;
                uint32_t t[4];
                ldsm_x4(t, uBh + off);
                bh[p * 2 + 0][0] = t[0]; bh[p * 2 + 0][1] = t[2];
                bh[p * 2 + 1][0] = t[1]; bh[p * 2 + 1][1] = t[3];
                ldsm_x4(t, uBl + off);
                bl[p * 2 + 0][0] = t[0]; bl[p * 2 + 0][1] = t[2];
                bl[p * 2 + 1][0] = t[1]; bl[p * 2 + 1][1] = t[3];
            }
#pragma unroll
            for (int mi = 0; mi < 4; mi++) {
                uint32_t off = ((wm + mi * 16 + lrow) * PADK + k0 + lk) * 2;
                uint32_t ah[4], al[4];
                ldsm_x4(ah, uAh + off);
                ldsm_x4(al, uAl + off);
#pragma unroll
                for (int ni = 0; ni < 4; ni++) {
                    mma_bf16(acc[mi][ni], ah, bh[ni]);
                    mma_bf16(acc[mi][ni], ah, bl[ni]);
                    mma_bf16(acc[mi][ni], al, bh[ni]);
                }
            }
        }
        __syncthreads();
    }

    // ---- epilogue: write C, optionally C2 = dinv^2*C + bc ----
#pragma unroll
    for (int mi = 0; mi < 4; mi++) {
        int row0 = bm + wm + mi * 16 + (lane >> 2);
        int row1 = row0 + 8;
        float d0 = 0.f, d1 = 0.f;
        if (C2) {
            if (row0 < NN) { d0 = g_dinv[row0]; d0 *= d0; }
            if (row1 < NN) { d1 = g_dinv[row1]; d1 *= d1; }
        }
#pragma unroll
        for (int ni = 0; ni < 4; ni++) {
            int col = bn + wn + ni * 8 + (lane & 3) * 2;
            float b0 = bias ? bias[col] : 0.f;
            float b1 = bias ? bias[col + 1] : 0.f;
            float v00 = acc[mi][ni][0] + b0, v01 = acc[mi][ni][1] + b1;
            float v10 = acc[mi][ni][2] + b0, v11 = acc[mi][ni][3] + b1;
            if (row0 < NN)
                *(float2*)(C + (size_t)row0 * HH + col) = make_float2(v00, v01);
            if (row1 < NN)
                *(float2*)(C + (size_t)row1 * HH + col) = make_float2(v10, v11);
            if (C2) {
                float c0 = bc[col], c1 = bc[col + 1];
                if (row0 < NN)
                    *(float2*)(C2 + (size_t)row0 * HH + col) =
                        make_float2(fmaf(d0, v00, c0), fmaf(d0, v01, c1));
                if (row1 < NN)
                    *(float2*)(C2 + (size_t)row1 * HH + col) =
                        make_float2(fmaf(d1, v10, c0), fmaf(d1, v11, c1));
            }
        }
    }
}

// ---------------- scatter ----------------
__global__ void k_scatter(const int* __restrict__ ei, const float* __restrict__ B,
                          float* __restrict__ A) {
    int g = blockIdx.x * blockDim.x + threadIdx.x;
    if (g >= EE * (HH / 4)) return;
    int e = g >> 7;
    int j = (g & 127) << 2;
    int is64 = g_is64;
    int src = is64 ? ei[2 * e] : ei[e];
    int dst = is64 ? ei[2 * EE + 2 * e] : ei[EE + e];
    float w = g_dinv[src] * g_dinv[dst];
    float4 v = *(const float4*)(B + (size_t)src * HH + j);
    float* out = A + (size_t)dst * HH + j;
    asm volatile("red.global.add.v4.f32 [%0], {%1, %2, %3, %4};"
                 :: "l"(out), "f"(w * v.x), "f"(w * v.y), "f"(w * v.z),
                    "f"(w * v.w)
                 : "memory");
}

// ---------------- batchnorm stats ----------------
__global__ void k_bnzero() {
    int i = threadIdx.x;
    g_colsum[i] = 0.f;
    g_colsq[i] = 0.f;
}

__global__ void k_bn_stats(const float* __restrict__ A) {
    int c = threadIdx.x;
    float s0 = 0.f, q0 = 0.f, s1 = 0.f, q1 = 0.f;
    for (int r = blockIdx.x; r < NN; r += gridDim.x) {
        const float* row = A + (size_t)r * HH;
        float v0 = row[c];
        float v1 = row[c + 256];
        s0 += v0; q0 += v0 * v0;
        s1 += v1; q1 += v1 * v1;
    }
    atomicAdd(&g_colsum[c], s0);
    atomicAdd(&g_colsq[c], q0);
    atomicAdd(&g_colsum[c + 256], s1);
    atomicAdd(&g_colsq[c + 256], q1);
}

__global__ void k_bn_final(const float* __restrict__ gamma,
                           const float* __restrict__ beta) {
    int c = threadIdx.x;
    float inv_n = 1.0f / (float)NN;
    float mean = g_colsum[c] * inv_n;
    float var = g_colsq[c] * inv_n - mean * mean;
    float sc = gamma[c] * rsqrtf(var + BN_EPS);
    g_scale[c] = sc;
    g_shift[c] = beta[c] - mean * sc;
}

// ---------------- fused tail ----------------
__global__ void k_weff(const float* __restrict__ W2, const float* __restrict__ b2,
                       const float* __restrict__ WO, const float* __restrict__ bO) {
    int b = blockIdx.x;
    const float* rowp = (b < HH) ? (W2 + (size_t)b * HH) : b2;
    float s = 0.f;
    for (int j = threadIdx.x; j < HH; j += 256) s += rowp[j] * WO[j];
#pragma unroll
    for (int o = 16; o; o >>= 1) s += __shfl_xor_sync(0xffffffffu, s, o);
    __shared__ float red[8];
    if ((threadIdx.x & 31) == 0) red[threadIdx.x >> 5] = s;
    __syncthreads();
    if (threadIdx.x == 0) {
        float t = 0.f;
        for (int i = 0; i < 8; i++) t += red[i];
        g_weff[b] = (b < HH) ? t : (t + bO[0]);
    }
}

// out[i] = sigmoid(dot(lrelu(scale*A[i]+shift), w_eff) + c_eff)
__global__ void k_out(const float* __restrict__ A, float* __restrict__ out) {
    int w = (blockIdx.x * blockDim.x + threadIdx.x) >> 5;
    int lane = threadIdx.x & 31;
    if (w >= NN) return;
    const float4* row = (const float4*)(A + (size_t)w * HH);
    const float4* wf = (const float4*)g_weff;
    const float4* sc4 = (const float4*)g_scale;
    const float4* sh4 = (const float4*)g_shift;
    float s = 0.f;
#pragma unroll
    for (int i = 0; i < 4; i++) {
        int idx = lane + 32 * i;
        float4 a = row[idx];
        float4 b = wf[idx];
        float4 sc = sc4[idx];
        float4 sh = sh4[idx];
        a.x = lrelu1(fmaf(sc.x, a.x, sh.x));
        a.y = lrelu1(fmaf(sc.y, a.y, sh.y));
        a.z = lrelu1(fmaf(sc.z, a.z, sh.z));
        a.w = lrelu1(fmaf(sc.w, a.w, sh.w));
        s += a.x * b.x + a.y * b.y + a.z * b.z + a.w * b.w;
    }
#pragma unroll
    for (int o = 16; o; o >>= 1) s += __shfl_xor_sync(0xffffffffu, s, o);
    if (lane == 0) {
        float t = s + g_weff[HH];
        out[w] = 1.0f / (1.0f + expf(-t));
    }
}

// ---------------- launcher ----------------
extern "C" void kernel_launch(void* const* d_in, const int* in_sizes, int n_in,
                              void* d_out, int out_size) {
    const float* x     = (const float*)d_in[0];
    const int*   ei    = (const int*)d_in[1];
    const float* W1    = (const float*)d_in[2];
    const float* b1    = (const float*)d_in[3];
    const float* Wc    = (const float*)d_in[4];
    const float* bc    = (const float*)d_in[5];
    const float* gamma = (const float*)d_in[6];
    const float* beta  = (const float*)d_in[7];
    const float* W2    = (const float*)d_in[8];
    const float* b2    = (const float*)d_in[9];
    const float* WO    = (const float*)d_in[10];
    const float* bO    = (const float*)d_in[11];
    float* out = (float*)d_out;

    float *pA, *pB, *pC, *pScale, *pShift;
    cudaGetSymbolAddress((void**)&pA, g_A);
    cudaGetSymbolAddress((void**)&pB, g_B);
    cudaGetSymbolAddress((void**)&pC, g_C);
    cudaGetSymbolAddress((void**)&pScale, g_scale);
    cudaGetSymbolAddress((void**)&pShift, g_shift);
    __nv_bfloat16 *w1h, *w1l, *wch, *wcl;
    cudaGetSymbolAddress((void**)&w1h, g_w1h);
    cudaGetSymbolAddress((void**)&w1l, g_w1l);
    cudaGetSymbolAddress((void**)&wch, g_wch);
    cudaGetSymbolAddress((void**)&wcl, g_wcl);

    k_prep<<<(NN + 255) / 256, 256>>>(ei);
    k_deg<<<(EE + 255) / 256, 256>>>(ei);
    k_dinv<<<(NN + 255) / 256, 256>>>();
    k_conv_w<<<HH, 256>>>(W1, w1h, w1l);
    k_conv_w<<<HH, 256>>>(Wc, wch, wcl);
    k_weff<<<HH + 1, 256>>>(W2, b2, WO, bO);

    const int nblk = ((NN + BM - 1) / BM) * 4;   // 3128, n-fastest swizzle
    const int edge4 = EE * (HH / 4);

    // h = x @ W1 + b1 -> A (raw)
    k_gemm_mma<<<nblk, 256>>>(x, w1h, w1l, b1, nullptr, nullptr, pA, nullptr,
                              nullptr);

    // layer 0: in=A(raw) -> B=h@Wc, C=agg-init; scatter into C; stats(C)
    k_gemm_mma<<<nblk, 256>>>(pA, wch, wcl, nullptr, nullptr, nullptr, pB, pC,
                              bc);
    k_scatter<<<(edge4 + 255) / 256, 256>>>(ei, pB, pC);
    k_bnzero<<<1, 512>>>();
    k_bn_stats<<<2048, 256>>>(pC);
    k_bn_final<<<1, 512>>>(gamma, beta);

    // layer 1: in=C with fused BN+LReLU -> B, A=agg-init; scatter into A
    k_gemm_mma<<<nblk, 256>>>(pC, wch, wcl, nullptr, pScale, pShift, pB, pA,
                              bc);
    k_scatter<<<(edge4 + 255) / 256, 256>>>(ei, pB, pA);
    k_bnzero<<<1, 512>>>();
    k_bn_stats<<<2048, 256>>>(pA);
    k_bn_final<<<1, 512>>>(gamma, beta);

    // fused tail: BN+LReLU + (W2@WO) dot + sigmoid
    k_out<<<(NN * 32 + 255) / 256, 256>>>(pA, out);
}

// round 6
// speedup vs baseline: 1.5476x; 1.5476x over previous
#include <cuda_runtime.h>
#include <cuda_bf16.h>
#include <cstdint>
#include <cstddef>

#define NN 100000
#define HH 512
#define EE 160000
#define BN_EPS 1e-5f
#define SLOPE 0.01f

// ---------------- scratch ----------------
__device__ float g_B[(size_t)NN * HH];
__device__ float g_C[(size_t)NN * HH];
__device__ __nv_bfloat16 g_Ah[(size_t)NN * HH];
__device__ __nv_bfloat16 g_Al[(size_t)NN * HH];
__device__ __nv_bfloat16 g_Bh[(size_t)NN * HH];
__device__ __nv_bfloat16 g_Bl[(size_t)NN * HH];
__device__ float g_dinv[NN];
__device__ int   g_deg[NN];
__device__ float g_colsum[HH];
__device__ float g_colsq[HH];
__device__ float g_scale[HH];
__device__ float g_shift[HH];
__device__ float g_weff[HH + 1];
__device__ int   g_is64;

__device__ __nv_bfloat16 g_w1h[HH * HH];
__device__ __nv_bfloat16 g_w1l[HH * HH];
__device__ __nv_bfloat16 g_wch[HH * HH];
__device__ __nv_bfloat16 g_wcl[HH * HH];

// ---------------- helpers ----------------
__device__ __forceinline__ uint32_t smem_u32(const void* p) {
    uint32_t a;
    asm("{ .reg .u64 t; cvta.to.shared.u64 t, %1; cvt.u32.u64 %0, t; }"
        : "=r"(a) : "l"(p));
    return a;
}
__device__ __forceinline__ void ldsm_x4(uint32_t* r, uint32_t addr) {
    asm volatile("ldmatrix.sync.aligned.m8n8.x4.shared.b16 {%0,%1,%2,%3}, [%4];"
                 : "=r"(r[0]), "=r"(r[1]), "=r"(r[2]), "=r"(r[3]) : "r"(addr));
}
__device__ __forceinline__ void mma_bf16(float* d, const uint32_t* a,
                                         const uint32_t* b) {
    asm volatile(
        "mma.sync.aligned.m16n8k16.row.col.f32.bf16.bf16.f32 "
        "{%0,%1,%2,%3}, {%4,%5,%6,%7}, {%8,%9}, {%0,%1,%2,%3};"
        : "+f"(d[0]), "+f"(d[1]), "+f"(d[2]), "+f"(d[3])
        : "r"(a[0]), "r"(a[1]), "r"(a[2]), "r"(a[3]), "r"(b[0]), "r"(b[1]));
}
__device__ __forceinline__ void cp16(uint32_t dst, const void* src) {
    asm volatile("cp.async.cg.shared.global [%0], [%1], 16;"
                 :: "r"(dst), "l"(src));
}
__device__ __forceinline__ float lrelu1(float x) {
    return x >= 0.f ? x : SLOPE * x;
}
__device__ __forceinline__ float4 xform(float4 v, int col,
                                        const float* __restrict__ scale,
                                        const float* __restrict__ shift) {
    float4 s = __ldg((const float4*)(scale + col));
    float4 t = __ldg((const float4*)(shift + col));
    v.x = lrelu1(fmaf(s.x, v.x, t.x));
    v.y = lrelu1(fmaf(s.y, v.y, t.y));
    v.z = lrelu1(fmaf(s.z, v.z, t.z));
    v.w = lrelu1(fmaf(s.w, v.w, t.w));
    return v;
}
__device__ __forceinline__ uint32_t packbf(float x, float y) {
    __nv_bfloat162 t = __floats2bfloat162_rn(x, y);
    return *(uint32_t*)&t;
}

// ---------------- setup ----------------
__global__ void k_prep(const int* __restrict__ ei) {
    int i = blockIdx.x * blockDim.x + threadIdx.x;
    if (i == 0)
        g_is64 = ((ei[1] | ei[3] | ei[5] | ei[7] | ei[9]) == 0) ? 1 : 0;
    if (i < NN) g_deg[i] = 0;
}
__global__ void k_deg(const int* __restrict__ ei) {
    int e = blockIdx.x * blockDim.x + threadIdx.x;
    if (e >= EE) return;
    int is64 = g_is64;
    int dst = is64 ? ei[2 * EE + 2 * e] : ei[EE + e];
    atomicAdd(&g_deg[dst], 1);
}
__global__ void k_dinv() {
    int i = blockIdx.x * blockDim.x + threadIdx.x;
    if (i < NN) g_dinv[i] = rsqrtf((float)g_deg[i] + 1.0f);
}
__global__ void k_conv_w(const float* __restrict__ W, __nv_bfloat16* __restrict__ Th,
                         __nv_bfloat16* __restrict__ Tl) {
    int k = blockIdx.x;
    for (int n = threadIdx.x; n < HH; n += blockDim.x) {
        float f = W[(size_t)k * HH + n];
        __nv_bfloat16 h = __float2bfloat16(f);
        float r = f - __bfloat162float(h);
        Th[(size_t)n * HH + k] = h;
        Tl[(size_t)n * HH + k] = __float2bfloat16(r);
    }
}

// split fp32 -> bf16 hi/lo, optional fused BN+LReLU
__global__ void k_split(const float4* __restrict__ in,
                        const float* __restrict__ scale,
                        const float* __restrict__ shift,
                        uint2* __restrict__ outh, uint2* __restrict__ outl) {
    int i = blockIdx.x * blockDim.x + threadIdx.x;
    if (i >= NN * (HH / 4)) return;
    float4 v = in[i];
    if (scale) {
        int c = (i & (HH / 4 - 1)) << 2;
        v = xform(v, c, scale, shift);
    }
    __nv_bfloat16 h0 = __float2bfloat16(v.x), h1 = __float2bfloat16(v.y);
    __nv_bfloat16 h2 = __float2bfloat16(v.z), h3 = __float2bfloat16(v.w);
    uint2 hp, lp;
    hp.x = ((uint32_t)__bfloat16_as_ushort(h0)) |
           ((uint32_t)__bfloat16_as_ushort(h1) << 16);
    hp.y = ((uint32_t)__bfloat16_as_ushort(h2)) |
           ((uint32_t)__bfloat16_as_ushort(h3) << 16);
    lp.x = packbf(v.x - __bfloat162float(h0), v.y - __bfloat162float(h1));
    lp.y = packbf(v.z - __bfloat162float(h2), v.w - __bfloat162float(h3));
    outh[i] = hp;
    outl[i] = lp;
}

// ---------------- GEMM: bf16 h/l split inputs, cp.async pipeline ----------
#define BM 128
#define BNT 128
#define BK 32
#define NCHUNK (HH / BK)   // 16
#define PADK 40            // 80B row stride: 16B-aligned, ldsm conflict-free
#define ROWB (PADK * 2)    // 80
#define OFF_AH 0
#define OFF_AL 10240
#define OFF_BH 20480
#define OFF_BL 30720
#define STG    40960
#define SMEMSZ (2 * STG)   // 81920

__global__ __launch_bounds__(256, 2)
void k_gemm(const __nv_bfloat16* __restrict__ Ah,
            const __nv_bfloat16* __restrict__ Al,
            const __nv_bfloat16* __restrict__ Wh,
            const __nv_bfloat16* __restrict__ Wl,
            const float* __restrict__ bias,
            float* __restrict__ Cf,            // fp32 out (or null)
            float* __restrict__ C2f,           // fp32 agg out (or null)
            const float* __restrict__ bc,      // agg bias
            __nv_bfloat16* __restrict__ Ch,    // bf16 h out (or null)
            __nv_bfloat16* __restrict__ Cl) {  // bf16 l out
    extern __shared__ char smem[];
    const uint32_t sbase = smem_u32(smem);
    const int tid = threadIdx.x;
    const int wid = tid >> 5;
    const int lane = tid & 31;
    const int bm = (blockIdx.x >> 2) * BM;
    const int bn = (blockIdx.x & 3) * BNT;
    const int wm = (wid & 1) * 64;
    const int wn = (wid >> 1) * 32;

    const char* pAh = (const char*)Ah;
    const char* pAl = (const char*)Al;
    const char* pWh = (const char*)Wh;
    const char* pWl = (const char*)Wl;

    float acc[4][4][4];
#pragma unroll
    for (int i = 0; i < 4; i++)
#pragma unroll
        for (int j = 0; j < 4; j++)
#pragma unroll
            for (int f = 0; f < 4; f++) acc[i][j][f] = 0.f;

#define ISSUE(s)                                                              \
    do {                                                                      \
        const uint32_t stu = sbase + ((s) & 1) * STG;                         \
        const size_t kb = (size_t)(s) * 64;                                   \
        _Pragma("unroll")                                                     \
        for (int i = 0; i < 2; i++) {                                         \
            int idx = tid + i * 256;                                          \
            int r = idx >> 2, c16 = (idx & 3) << 4;                           \
            int grow = bm + r;                                                \
            if (grow < NN) {                                                  \
                size_t ab = (size_t)grow * (HH * 2) + kb + c16;               \
                cp16(stu + OFF_AH + r * ROWB + c16, pAh + ab);                \
                cp16(stu + OFF_AL + r * ROWB + c16, pAl + ab);                \
            }                                                                 \
            size_t wb = (size_t)(bn + r) * (HH * 2) + kb + c16;               \
            cp16(stu + OFF_BH + r * ROWB + c16, pWh + wb);                    \
            cp16(stu + OFF_BL + r * ROWB + c16, pWl + wb);                    \
        }                                                                     \
    } while (0)

    ISSUE(0);
    asm volatile("cp.async.commit_group;" ::: "memory");

    for (int s = 0; s < NCHUNK; s++) {
        if (s > 0) __syncthreads();             // buffer (s+1)&1 free
        if (s + 1 < NCHUNK) ISSUE(s + 1);
        asm volatile("cp.async.commit_group;" ::: "memory");
        asm volatile("cp.async.wait_group 1;" ::: "memory");  // stage s ready
        __syncthreads();

        const uint32_t stu = sbase + (s & 1) * STG;
        const uint32_t lrow = (lane & 15);
        const uint32_t lk = (lane >> 4) * 8;
#pragma unroll
        for (int ks = 0; ks < 2; ks++) {
            const int k0 = ks * 16;
            uint32_t bh[4][2], bl[4][2];
#pragma unroll
            for (int p = 0; p < 2; p++) {
                uint32_t off = ((wn + p * 16 + lrow) * PADK + k0 + lk) * 2;
                uint32_t t[4];
                ldsm_x4(t, stu + OFF_BH + off);
                bh[p * 2 + 0][0] = t[0]; bh[p * 2 + 0][1] = t[2];
                bh[p * 2 + 1][0] = t[1]; bh[p * 2 + 1][1] = t[3];
                ldsm_x4(t, stu + OFF_BL + off);
                bl[p * 2 + 0][0] = t[0]; bl[p * 2 + 0][1] = t[2];
                bl[p * 2 + 1][0] = t[1]; bl[p * 2 + 1][1] = t[3];
            }
#pragma unroll
            for (int mi = 0; mi < 4; mi++) {
                uint32_t off = ((wm + mi * 16 + lrow) * PADK + k0 + lk) * 2;
                uint32_t ah[4], al[4];
                ldsm_x4(ah, stu + OFF_AH + off);
                ldsm_x4(al, stu + OFF_AL + off);
#pragma unroll
                for (int ni = 0; ni < 4; ni++) {
                    mma_bf16(acc[mi][ni], ah, bh[ni]);
                    mma_bf16(acc[mi][ni], ah, bl[ni]);
                    mma_bf16(acc[mi][ni], al, bh[ni]);
                }
            }
        }
    }

    // ---- epilogue ----
#pragma unroll
    for (int mi = 0; mi < 4; mi++) {
        int row0 = bm + wm + mi * 16 + (lane >> 2);
        int row1 = row0 + 8;
        float d0 = 0.f, d1 = 0.f;
        if (C2f) {
            if (row0 < NN) { d0 = g_dinv[row0]; d0 *= d0; }
            if (row1 < NN) { d1 = g_dinv[row1]; d1 *= d1; }
        }
#pragma unroll
        for (int ni = 0; ni < 4; ni++) {
            int col = bn + wn + ni * 8 + (lane & 3) * 2;
            float b0 = bias ? bias[col] : 0.f;
            float b1 = bias ? bias[col + 1] : 0.f;
            float v00 = acc[mi][ni][0] + b0, v01 = acc[mi][ni][1] + b1;
            float v10 = acc[mi][ni][2] + b0, v11 = acc[mi][ni][3] + b1;
            if (Ch) {   // bf16 split output
                if (row0 < NN) {
                    __nv_bfloat16 h0 = __float2bfloat16(v00);
                    __nv_bfloat16 h1 = __float2bfloat16(v01);
                    *(uint32_t*)(Ch + (size_t)row0 * HH + col) =
                        ((uint32_t)__bfloat16_as_ushort(h0)) |
                        ((uint32_t)__bfloat16_as_ushort(h1) << 16);
                    *(uint32_t*)(Cl + (size_t)row0 * HH + col) =
                        packbf(v00 - __bfloat162float(h0),
                               v01 - __bfloat162float(h1));
                }
                if (row1 < NN) {
                    __nv_bfloat16 h0 = __float2bfloat16(v10);
                    __nv_bfloat16 h1 = __float2bfloat16(v11);
                    *(uint32_t*)(Ch + (size_t)row1 * HH + col) =
                        ((uint32_t)__bfloat16_as_ushort(h0)) |
                        ((uint32_t)__bfloat16_as_ushort(h1) << 16);
                    *(uint32_t*)(Cl + (size_t)row1 * HH + col) =
                        packbf(v10 - __bfloat162float(h0),
                               v11 - __bfloat162float(h1));
                }
            } else {
                if (row0 < NN)
                    *(float2*)(Cf + (size_t)row0 * HH + col) =
                        make_float2(v00, v01);
                if (row1 < NN)
                    *(float2*)(Cf + (size_t)row1 * HH + col) =
                        make_float2(v10, v11);
                if (C2f) {
                    float c0 = bc[col], c1 = bc[col + 1];
                    if (row0 < NN)
                        *(float2*)(C2f + (size_t)row0 * HH + col) =
                            make_float2(fmaf(d0, v00, c0), fmaf(d0, v01, c1));
                    if (row1 < NN)
                        *(float2*)(C2f + (size_t)row1 * HH + col) =
                            make_float2(fmaf(d1, v10, c0), fmaf(d1, v11, c1));
                }
            }
        }
    }
}

// ---------------- scatter ----------------
__global__ void k_scatter(const int* __restrict__ ei, const float* __restrict__ B,
                          float* __restrict__ A) {
    int g = blockIdx.x * blockDim.x + threadIdx.x;
    if (g >= EE * (HH / 4)) return;
    int e = g >> 7;
    int j = (g & 127) << 2;
    int is64 = g_is64;
    int src = is64 ? ei[2 * e] : ei[e];
    int dst = is64 ? ei[2 * EE + 2 * e] : ei[EE + e];
    float w = g_dinv[src] * g_dinv[dst];
    float4 v = *(const float4*)(B + (size_t)src * HH + j);
    float* out = A + (size_t)dst * HH + j;
    asm volatile("red.global.add.v4.f32 [%0], {%1, %2, %3, %4};"
                 :: "l"(out), "f"(w * v.x), "f"(w * v.y), "f"(w * v.z),
                    "f"(w * v.w)
                 : "memory");
}

// ---------------- batchnorm stats ----------------
__global__ void k_bnzero() {
    int i = threadIdx.x;
    g_colsum[i] = 0.f;
    g_colsq[i] = 0.f;
}
__global__ void k_bn_stats(const float* __restrict__ A) {
    int c = threadIdx.x;
    float s0 = 0.f, q0 = 0.f, s1 = 0.f, q1 = 0.f;
    for (int r = blockIdx.x; r < NN; r += gridDim.x) {
        const float* row = A + (size_t)r * HH;
        float v0 = row[c];
        float v1 = row[c + 256];
        s0 += v0; q0 += v0 * v0;
        s1 += v1; q1 += v1 * v1;
    }
    atomicAdd(&g_colsum[c], s0);
    atomicAdd(&g_colsq[c], q0);
    atomicAdd(&g_colsum[c + 256], s1);
    atomicAdd(&g_colsq[c + 256], q1);
}
__global__ void k_bn_final(const float* __restrict__ gamma,
                           const float* __restrict__ beta) {
    int c = threadIdx.x;
    float inv_n = 1.0f / (float)NN;
    float mean = g_colsum[c] * inv_n;
    float var = g_colsq[c] * inv_n - mean * mean;
    float sc = gamma[c] * rsqrtf(var + BN_EPS);
    g_scale[c] = sc;
    g_shift[c] = beta[c] - mean * sc;
}

// ---------------- fused tail ----------------
__global__ void k_weff(const float* __restrict__ W2, const float* __restrict__ b2,
                       const float* __restrict__ WO, const float* __restrict__ bO) {
    int b = blockIdx.x;
    const float* rowp = (b < HH) ? (W2 + (size_t)b * HH) : b2;
    float s = 0.f;
    for (int j = threadIdx.x; j < HH; j += 256) s += rowp[j] * WO[j];
#pragma unroll
    for (int o = 16; o; o >>= 1) s += __shfl_xor_sync(0xffffffffu, s, o);
    __shared__ float red[8];
    if ((threadIdx.x & 31) == 0) red[threadIdx.x >> 5] = s;
    __syncthreads();
    if (threadIdx.x == 0) {
        float t = 0.f;
        for (int i = 0; i < 8; i++) t += red[i];
        g_weff[b] = (b < HH) ? t : (t + bO[0]);
    }
}

__global__ void k_out(const float* __restrict__ A, float* __restrict__ out) {
    int w = (blockIdx.x * blockDim.x + threadIdx.x) >> 5;
    int lane = threadIdx.x & 31;
    if (w >= NN) return;
    const float4* row = (const float4*)(A + (size_t)w * HH);
    const float4* wf = (const float4*)g_weff;
    const float4* sc4 = (const float4*)g_scale;
    const float4* sh4 = (const float4*)g_shift;
    float s = 0.f;
#pragma unroll
    for (int i = 0; i < 4; i++) {
        int idx = lane + 32 * i;
        float4 a = row[idx];
        float4 b = wf[idx];
        float4 sc = sc4[idx];
        float4 sh = sh4[idx];
        a.x = lrelu1(fmaf(sc.x, a.x, sh.x));
        a.y = lrelu1(fmaf(sc.y, a.y, sh.y));
        a.z = lrelu1(fmaf(sc.z, a.z, sh.z));
        a.w = lrelu1(fmaf(sc.w, a.w, sh.w));
        s += a.x * b.x + a.y * b.y + a.z * b.z + a.w * b.w;
    }
#pragma unroll
    for (int o = 16; o; o >>= 1) s += __shfl_xor_sync(0xffffffffu, s, o);
    if (lane == 0) {
        float t = s + g_weff[HH];
        out[w] = 1.0f / (1.0f + expf(-t));
    }
}

// ---------------- launcher ----------------
extern "C" void kernel_launch(void* const* d_in, const int* in_sizes, int n_in,
                              void* d_out, int out_size) {
    const float* x     = (const float*)d_in[0];
    const int*   ei    = (const int*)d_in[1];
    const float* W1    = (const float*)d_in[2];
    const float* b1    = (const float*)d_in[3];
    const float* Wc    = (const float*)d_in[4];
    const float* bc    = (const float*)d_in[5];
    const float* gamma = (const float*)d_in[6];
    const float* beta  = (const float*)d_in[7];
    const float* W2    = (const float*)d_in[8];
    const float* b2    = (const float*)d_in[9];
    const float* WO    = (const float*)d_in[10];
    const float* bO    = (const float*)d_in[11];
    float* out = (float*)d_out;

    float *pB, *pC, *pScale, *pShift;
    cudaGetSymbolAddress((void**)&pB, g_B);
    cudaGetSymbolAddress((void**)&pC, g_C);
    cudaGetSymbolAddress((void**)&pScale, g_scale);
    cudaGetSymbolAddress((void**)&pShift, g_shift);
    __nv_bfloat16 *pAh, *pAl, *pBh, *pBl, *w1h, *w1l, *wch, *wcl;
    cudaGetSymbolAddress((void**)&pAh, g_Ah);
    cudaGetSymbolAddress((void**)&pAl, g_Al);
    cudaGetSymbolAddress((void**)&pBh, g_Bh);
    cudaGetSymbolAddress((void**)&pBl, g_Bl);
    cudaGetSymbolAddress((void**)&w1h, g_w1h);
    cudaGetSymbolAddress((void**)&w1l, g_w1l);
    cudaGetSymbolAddress((void**)&wch, g_wch);
    cudaGetSymbolAddress((void**)&wcl, g_wcl);

    cudaFuncSetAttribute(k_gemm, cudaFuncAttributeMaxDynamicSharedMemorySize,
                         SMEMSZ);

    k_prep<<<(NN + 255) / 256, 256>>>(ei);
    k_deg<<<(EE + 255) / 256, 256>>>(ei);
    k_dinv<<<(NN + 255) / 256, 256>>>();
    k_conv_w<<<HH, 256>>>(W1, w1h, w1l);
    k_conv_w<<<HH, 256>>>(Wc, wch, wcl);
    k_weff<<<HH + 1, 256>>>(W2, b2, WO, bO);

    const int nblk = ((NN + BM - 1) / BM) * 4;   // 3128
    const int elem4 = NN * (HH / 4);
    const int edge4 = EE * (HH / 4);

    // split x -> bf16 h/l
    k_split<<<(elem4 + 255) / 256, 256>>>((const float4*)x, nullptr, nullptr,
                                          (uint2*)pAh, (uint2*)pAl);

    // GEMM1: h = x@W1 + b1, bf16 split output
    k_gemm<<<nblk, 256, SMEMSZ>>>(pAh, pAl, w1h, w1l, b1, nullptr, nullptr,
                                  nullptr, pBh, pBl);

    // layer 0: B = h@Wc (fp32) + C = agg-init; scatter; stats
    k_gemm<<<nblk, 256, SMEMSZ>>>(pBh, pBl, wch, wcl, nullptr, pB, pC, bc,
                                  nullptr, nullptr);
    k_scatter<<<(edge4 + 255) / 256, 256>>>(ei, pB, pC);
    k_bnzero<<<1, 512>>>();
    k_bn_stats<<<2048, 256>>>(pC);
    k_bn_final<<<1, 512>>>(gamma, beta);

    // split C with fused BN+LReLU -> bf16 h/l
    k_split<<<(elem4 + 255) / 256, 256>>>((const float4*)pC, pScale, pShift,
                                          (uint2*)pAh, (uint2*)pAl);

    // layer 1
    k_gemm<<<nblk, 256, SMEMSZ>>>(pAh, pAl, wch, wcl, nullptr, pB, pC, bc,
                                  nullptr, nullptr);
    k_scatter<<<(edge4 + 255) / 256, 256>>>(ei, pB, pC);
    k_bnzero<<<1, 512>>>();
    k_bn_stats<<<2048, 256>>>(pC);
    k_bn_final<<<1, 512>>>(gamma, beta);

    // fused tail
    k_out<<<(NN * 32 + 255) / 256, 256>>>(pC, out);
}

// round 7
// speedup vs baseline: 1.9490x; 1.2594x over previous
#include <cuda_runtime.h>
#include <cuda_fp16.h>
#include <cstdint>
#include <cstddef>

#define NN 100000
#define HH 512
#define EE 160000
#define BN_EPS 1e-5f
#define SLOPE 0.01f

// ---------------- scratch ----------------
__device__ float g_B[(size_t)NN * HH];
__device__ float g_C[(size_t)NN * HH];
__device__ __half g_Ah[(size_t)NN * HH];
__device__ __half g_Al[(size_t)NN * HH];
__device__ __half g_Bh[(size_t)NN * HH];
__device__ __half g_Bl[(size_t)NN * HH];
__device__ float g_dinv[NN];
__device__ int   g_deg[NN];
__device__ float g_colsum[HH];
__device__ float g_colsq[HH];
__device__ float g_scale[HH];
__device__ float g_shift[HH];
__device__ float g_weff[HH + 1];
__device__ int   g_is64;

// transposed fp16 weights: T[n][k] = fp16(W[k][n])  (no lo half needed)
__device__ __half g_w1h[HH * HH];
__device__ __half g_wch[HH * HH];

// ---------------- helpers ----------------
__device__ __forceinline__ uint32_t smem_u32(const void* p) {
    uint32_t a;
    asm("{ .reg .u64 t; cvta.to.shared.u64 t, %1; cvt.u32.u64 %0, t; }"
        : "=r"(a) : "l"(p));
    return a;
}
__device__ __forceinline__ void ldsm_x4(uint32_t* r, uint32_t addr) {
    asm volatile("ldmatrix.sync.aligned.m8n8.x4.shared.b16 {%0,%1,%2,%3}, [%4];"
                 : "=r"(r[0]), "=r"(r[1]), "=r"(r[2]), "=r"(r[3]) : "r"(addr));
}
__device__ __forceinline__ void mma_f16(float* d, const uint32_t* a,
                                        const uint32_t* b) {
    asm volatile(
        "mma.sync.aligned.m16n8k16.row.col.f32.f16.f16.f32 "
        "{%0,%1,%2,%3}, {%4,%5,%6,%7}, {%8,%9}, {%0,%1,%2,%3};"
        : "+f"(d[0]), "+f"(d[1]), "+f"(d[2]), "+f"(d[3])
        : "r"(a[0]), "r"(a[1]), "r"(a[2]), "r"(a[3]), "r"(b[0]), "r"(b[1]));
}
__device__ __forceinline__ void cp16(uint32_t dst, const void* src) {
    asm volatile("cp.async.cg.shared.global [%0], [%1], 16;"
                 :: "r"(dst), "l"(src));
}
__device__ __forceinline__ float lrelu1(float x) {
    return x >= 0.f ? x : SLOPE * x;
}
__device__ __forceinline__ float4 xform(float4 v, int col,
                                        const float* __restrict__ scale,
                                        const float* __restrict__ shift) {
    float4 s = __ldg((const float4*)(scale + col));
    float4 t = __ldg((const float4*)(shift + col));
    v.x = lrelu1(fmaf(s.x, v.x, t.x));
    v.y = lrelu1(fmaf(s.y, v.y, t.y));
    v.z = lrelu1(fmaf(s.z, v.z, t.z));
    v.w = lrelu1(fmaf(s.w, v.w, t.w));
    return v;
}
__device__ __forceinline__ uint32_t packh(__half a, __half b) {
    return ((uint32_t)__half_as_ushort(a)) |
           ((uint32_t)__half_as_ushort(b) << 16);
}

// ---------------- setup ----------------
__global__ void k_prep(const int* __restrict__ ei) {
    int i = blockIdx.x * blockDim.x + threadIdx.x;
    if (i == 0)
        g_is64 = ((ei[1] | ei[3] | ei[5] | ei[7] | ei[9]) == 0) ? 1 : 0;
    if (i < NN) g_deg[i] = 0;
}
__global__ void k_deg(const int* __restrict__ ei) {
    int e = blockIdx.x * blockDim.x + threadIdx.x;
    if (e >= EE) return;
    int is64 = g_is64;
    int dst = is64 ? ei[2 * EE + 2 * e] : ei[EE + e];
    atomicAdd(&g_deg[dst], 1);
}
__global__ void k_dinv() {
    int i = blockIdx.x * blockDim.x + threadIdx.x;
    if (i < NN) g_dinv[i] = rsqrtf((float)g_deg[i] + 1.0f);
}
__global__ void k_conv_w(const float* __restrict__ W, __half* __restrict__ Th) {
    int k = blockIdx.x;
    for (int n = threadIdx.x; n < HH; n += blockDim.x)
        Th[(size_t)n * HH + k] = __float2half_rn(W[(size_t)k * HH + n]);
}

// split fp32 -> fp16 hi/lo, optional fused BN+LReLU
__global__ void k_split(const float4* __restrict__ in,
                        const float* __restrict__ scale,
                        const float* __restrict__ shift,
                        uint2* __restrict__ outh, uint2* __restrict__ outl) {
    int i = blockIdx.x * blockDim.x + threadIdx.x;
    if (i >= NN * (HH / 4)) return;
    float4 v = in[i];
    if (scale) {
        int c = (i & (HH / 4 - 1)) << 2;
        v = xform(v, c, scale, shift);
    }
    __half h0 = __float2half_rn(v.x), h1 = __float2half_rn(v.y);
    __half h2 = __float2half_rn(v.z), h3 = __float2half_rn(v.w);
    uint2 hp, lp;
    hp.x = packh(h0, h1);
    hp.y = packh(h2, h3);
    lp.x = packh(__float2half_rn(v.x - __half2float(h0)),
                 __float2half_rn(v.y - __half2float(h1)));
    lp.y = packh(__float2half_rn(v.z - __half2float(h2)),
                 __float2half_rn(v.w - __half2float(h3)));
    outh[i] = hp;
    outl[i] = lp;
}

// ---------------- GEMM: fp16 2-term (A exact, W rounded) -------------------
#define BM 128
#define BNT 128
#define BK 32
#define NCHUNK (HH / BK)   // 16
#define PADK 40            // 80B row stride
#define ROWB (PADK * 2)
#define OFF_AH 0
#define OFF_AL 10240
#define OFF_BH 20480
#define STG    30720
#define SMEMSZ (2 * STG)   // 61440

__global__ __launch_bounds__(256, 2)
void k_gemm(const __half* __restrict__ Ah,
            const __half* __restrict__ Al,
            const __half* __restrict__ Wh,
            const float* __restrict__ bias,
            float* __restrict__ Cf,            // fp32 out (or null)
            float* __restrict__ C2f,           // fp32 agg out (or null)
            const float* __restrict__ bc,      // agg bias
            __half* __restrict__ Ch,           // fp16 h out (or null)
            __half* __restrict__ Cl) {         // fp16 l out
    extern __shared__ char smem[];
    const uint32_t sbase = smem_u32(smem);
    const int tid = threadIdx.x;
    const int wid = tid >> 5;
    const int lane = tid & 31;
    const int bm = (blockIdx.x >> 2) * BM;
    const int bn = (blockIdx.x & 3) * BNT;
    const int wm = (wid & 1) * 64;
    const int wn = (wid >> 1) * 32;

    const char* pAh = (const char*)Ah;
    const char* pAl = (const char*)Al;
    const char* pWh = (const char*)Wh;

    float acc[4][4][4];
#pragma unroll
    for (int i = 0; i < 4; i++)
#pragma unroll
        for (int j = 0; j < 4; j++)
#pragma unroll
            for (int f = 0; f < 4; f++) acc[i][j][f] = 0.f;

#define ISSUE(s)                                                              \
    do {                                                                      \
        const uint32_t stu = sbase + ((s) & 1) * STG;                         \
        const size_t kb = (size_t)(s) * 64;                                   \
        _Pragma("unroll")                                                     \
        for (int i = 0; i < 2; i++) {                                         \
            int idx = tid + i * 256;                                          \
            int r = idx >> 2, c16 = (idx & 3) << 4;                           \
            int grow = bm + r;                                                \
            if (grow < NN) {                                                  \
                size_t ab = (size_t)grow * (HH * 2) + kb + c16;               \
                cp16(stu + OFF_AH + r * ROWB + c16, pAh + ab);                \
                cp16(stu + OFF_AL + r * ROWB + c16, pAl + ab);                \
            }                                                                 \
            size_t wb = (size_t)(bn + r) * (HH * 2) + kb + c16;               \
            cp16(stu + OFF_BH + r * ROWB + c16, pWh + wb);                    \
        }                                                                     \
    } while (0)

    ISSUE(0);
    asm volatile("cp.async.commit_group;" ::: "memory");

    for (int s = 0; s < NCHUNK; s++) {
        if (s > 0) __syncthreads();
        if (s + 1 < NCHUNK) ISSUE(s + 1);
        asm volatile("cp.async.commit_group;" ::: "memory");
        asm volatile("cp.async.wait_group 1;" ::: "memory");
        __syncthreads();

        const uint32_t stu = sbase + (s & 1) * STG;
        const uint32_t lrow = (lane & 15);
        const uint32_t lk = (lane >> 4) * 8;
#pragma unroll
        for (int ks = 0; ks < 2; ks++) {
            const int k0 = ks * 16;
            uint32_t bh[4][2];
#pragma unroll
            for (int p = 0; p < 2; p++) {
                uint32_t off = ((wn + p * 16 + lrow) * PADK + k0 + lk) * 2;
                uint32_t t[4];
                ldsm_x4(t, stu + OFF_BH + off);
                bh[p * 2 + 0][0] = t[0]; bh[p * 2 + 0][1] = t[2];
                bh[p * 2 + 1][0] = t[1]; bh[p * 2 + 1][1] = t[3];
            }
#pragma unroll
            for (int mi = 0; mi < 4; mi++) {
                uint32_t off = ((wm + mi * 16 + lrow) * PADK + k0 + lk) * 2;
                uint32_t ah[4], al[4];
                ldsm_x4(ah, stu + OFF_AH + off);
                ldsm_x4(al, stu + OFF_AL + off);
#pragma unroll
                for (int ni = 0; ni < 4; ni++) {
                    mma_f16(acc[mi][ni], ah, bh[ni]);
                    mma_f16(acc[mi][ni], al, bh[ni]);
                }
            }
        }
    }

    // ---- epilogue ----
#pragma unroll
    for (int mi = 0; mi < 4; mi++) {
        int row0 = bm + wm + mi * 16 + (lane >> 2);
        int row1 = row0 + 8;
        float d0 = 0.f, d1 = 0.f;
        if (C2f) {
            if (row0 < NN) { d0 = g_dinv[row0]; d0 *= d0; }
            if (row1 < NN) { d1 = g_dinv[row1]; d1 *= d1; }
        }
#pragma unroll
        for (int ni = 0; ni < 4; ni++) {
            int col = bn + wn + ni * 8 + (lane & 3) * 2;
            float b0 = bias ? bias[col] : 0.f;
            float b1 = bias ? bias[col + 1] : 0.f;
            float v00 = acc[mi][ni][0] + b0, v01 = acc[mi][ni][1] + b1;
            float v10 = acc[mi][ni][2] + b0, v11 = acc[mi][ni][3] + b1;
            if (Ch) {
                if (row0 < NN) {
                    __half h0 = __float2half_rn(v00);
                    __half h1 = __float2half_rn(v01);
                    *(uint32_t*)(Ch + (size_t)row0 * HH + col) = packh(h0, h1);
                    *(uint32_t*)(Cl + (size_t)row0 * HH + col) =
                        packh(__float2half_rn(v00 - __half2float(h0)),
                              __float2half_rn(v01 - __half2float(h1)));
                }
                if (row1 < NN) {
                    __half h0 = __float2half_rn(v10);
                    __half h1 = __float2half_rn(v11);
                    *(uint32_t*)(Ch + (size_t)row1 * HH + col) = packh(h0, h1);
                    *(uint32_t*)(Cl + (size_t)row1 * HH + col) =
                        packh(__float2half_rn(v10 - __half2float(h0)),
                              __float2half_rn(v11 - __half2float(h1)));
                }
            } else {
                if (row0 < NN)
                    *(float2*)(Cf + (size_t)row0 * HH + col) =
                        make_float2(v00, v01);
                if (row1 < NN)
                    *(float2*)(Cf + (size_t)row1 * HH + col) =
                        make_float2(v10, v11);
                if (C2f) {
                    float c0 = bc[col], c1 = bc[col + 1];
                    if (row0 < NN)
                        *(float2*)(C2f + (size_t)row0 * HH + col) =
                            make_float2(fmaf(d0, v00, c0), fmaf(d0, v01, c1));
                    if (row1 < NN)
                        *(float2*)(C2f + (size_t)row1 * HH + col) =
                            make_float2(fmaf(d1, v10, c0), fmaf(d1, v11, c1));
                }
            }
        }
    }
}

// ---------------- scatter ----------------
__global__ void k_scatter(const int* __restrict__ ei, const float* __restrict__ B,
                          float* __restrict__ A) {
    int g = blockIdx.x * blockDim.x + threadIdx.x;
    if (g >= EE * (HH / 4)) return;
    int e = g >> 7;
    int j = (g & 127) << 2;
    int is64 = g_is64;
    int src = is64 ? ei[2 * e] : ei[e];
    int dst = is64 ? ei[2 * EE + 2 * e] : ei[EE + e];
    float w = g_dinv[src] * g_dinv[dst];
    float4 v = *(const float4*)(B + (size_t)src * HH + j);
    float* out = A + (size_t)dst * HH + j;
    asm volatile("red.global.add.v4.f32 [%0], {%1, %2, %3, %4};"
                 :: "l"(out), "f"(w * v.x), "f"(w * v.y), "f"(w * v.z),
                    "f"(w * v.w)
                 : "memory");
}

// ---------------- batchnorm stats ----------------
__global__ void k_bnzero() {
    int i = threadIdx.x;
    g_colsum[i] = 0.f;
    g_colsq[i] = 0.f;
}
__global__ void k_bn_stats(const float* __restrict__ A) {
    int c = threadIdx.x;
    float s0 = 0.f, q0 = 0.f, s1 = 0.f, q1 = 0.f;
    for (int r = blockIdx.x; r < NN; r += gridDim.x) {
        const float* row = A + (size_t)r * HH;
        float v0 = row[c];
        float v1 = row[c + 256];
        s0 += v0; q0 += v0 * v0;
        s1 += v1; q1 += v1 * v1;
    }
    atomicAdd(&g_colsum[c], s0);
    atomicAdd(&g_colsq[c], q0);
    atomicAdd(&g_colsum[c + 256], s1);
    atomicAdd(&g_colsq[c + 256], q1);
}
__global__ void k_bn_final(const float* __restrict__ gamma,
                           const float* __restrict__ beta) {
    int c = threadIdx.x;
    float inv_n = 1.0f / (float)NN;
    float mean = g_colsum[c] * inv_n;
    float var = g_colsq[c] * inv_n - mean * mean;
    float sc = gamma[c] * rsqrtf(var + BN_EPS);
    g_scale[c] = sc;
    g_shift[c] = beta[c] - mean * sc;
}

// ---------------- fused tail ----------------
__global__ void k_weff(const float* __restrict__ W2, const float* __restrict__ b2,
                       const float* __restrict__ WO, const float* __restrict__ bO) {
    int b = blockIdx.x;
    const float* rowp = (b < HH) ? (W2 + (size_t)b * HH) : b2;
    float s = 0.f;
    for (int j = threadIdx.x; j < HH; j += 256) s += rowp[j] * WO[j];
#pragma unroll
    for (int o = 16; o; o >>= 1) s += __shfl_xor_sync(0xffffffffu, s, o);
    __shared__ float red[8];
    if ((threadIdx.x & 31) == 0) red[threadIdx.x >> 5] = s;
    __syncthreads();
    if (threadIdx.x == 0) {
        float t = 0.f;
        for (int i = 0; i < 8; i++) t += red[i];
        g_weff[b] = (b < HH) ? t : (t + bO[0]);
    }
}

__global__ void k_out(const float* __restrict__ A, float* __restrict__ out) {
    int w = (blockIdx.x * blockDim.x + threadIdx.x) >> 5;
    int lane = threadIdx.x & 31;
    if (w >= NN) return;
    const float4* row = (const float4*)(A + (size_t)w * HH);
    const float4* wf = (const float4*)g_weff;
    const float4* sc4 = (const float4*)g_scale;
    const float4* sh4 = (const float4*)g_shift;
    float s = 0.f;
#pragma unroll
    for (int i = 0; i < 4; i++) {
        int idx = lane + 32 * i;
        float4 a = row[idx];
        float4 b = wf[idx];
        float4 sc = sc4[idx];
        float4 sh = sh4[idx];
        a.x = lrelu1(fmaf(sc.x, a.x, sh.x));
        a.y = lrelu1(fmaf(sc.y, a.y, sh.y));
        a.z = lrelu1(fmaf(sc.z, a.z, sh.z));
        a.w = lrelu1(fmaf(sc.w, a.w, sh.w));
        s += a.x * b.x + a.y * b.y + a.z * b.z + a.w * b.w;
    }
#pragma unroll
    for (int o = 16; o; o >>= 1) s += __shfl_xor_sync(0xffffffffu, s, o);
    if (lane == 0) {
        float t = s + g_weff[HH];
        out[w] = 1.0f / (1.0f + expf(-t));
    }
}

// ---------------- launcher ----------------
extern "C" void kernel_launch(void* const* d_in, const int* in_sizes, int n_in,
                              void* d_out, int out_size) {
    const float* x     = (const float*)d_in[0];
    const int*   ei    = (const int*)d_in[1];
    const float* W1    = (const float*)d_in[2];
    const float* b1    = (const float*)d_in[3];
    const float* Wc    = (const float*)d_in[4];
    const float* bc    = (const float*)d_in[5];
    const float* gamma = (const float*)d_in[6];
    const float* beta  = (const float*)d_in[7];
    const float* W2    = (const float*)d_in[8];
    const float* b2    = (const float*)d_in[9];
    const float* WO    = (const float*)d_in[10];
    const float* bO    = (const float*)d_in[11];
    float* out = (float*)d_out;

    float *pB, *pC, *pScale, *pShift;
    cudaGetSymbolAddress((void**)&pB, g_B);
    cudaGetSymbolAddress((void**)&pC, g_C);
    cudaGetSymbolAddress((void**)&pScale, g_scale);
    cudaGetSymbolAddress((void**)&pShift, g_shift);
    __half *pAh, *pAl, *pBh, *pBl, *w1h, *wch;
    cudaGetSymbolAddress((void**)&pAh, g_Ah);
    cudaGetSymbolAddress((void**)&pAl, g_Al);
    cudaGetSymbolAddress((void**)&pBh, g_Bh);
    cudaGetSymbolAddress((void**)&pBl, g_Bl);
    cudaGetSymbolAddress((void**)&w1h, g_w1h);
    cudaGetSymbolAddress((void**)&wch, g_wch);

    cudaFuncSetAttribute(k_gemm, cudaFuncAttributeMaxDynamicSharedMemorySize,
                         SMEMSZ);

    k_prep<<<(NN + 255) / 256, 256>>>(ei);
    k_deg<<<(EE + 255) / 256, 256>>>(ei);
    k_dinv<<<(NN + 255) / 256, 256>>>();
    k_conv_w<<<HH, 256>>>(W1, w1h);
    k_conv_w<<<HH, 256>>>(Wc, wch);
    k_weff<<<HH + 1, 256>>>(W2, b2, WO, bO);

    const int nblk = ((NN + BM - 1) / BM) * 4;   // 3128
    const int elem4 = NN * (HH / 4);
    const int edge4 = EE * (HH / 4);

    // split x -> fp16 h/l
    k_split<<<(elem4 + 255) / 256, 256>>>((const float4*)x, nullptr, nullptr,
                                          (uint2*)pAh, (uint2*)pAl);

    // GEMM1: h = x@W1 + b1, fp16 split output
    k_gemm<<<nblk, 256, SMEMSZ>>>(pAh, pAl, w1h, b1, nullptr, nullptr,
                                  nullptr, pBh, pBl);

    // layer 0: B = h@Wc (fp32) + C = agg-init; scatter; stats
    k_gemm<<<nblk, 256, SMEMSZ>>>(pBh, pBl, wch, nullptr, pB, pC, bc,
                                  nullptr, nullptr);
    k_scatter<<<(edge4 + 255) / 256, 256>>>(ei, pB, pC);
    k_bnzero<<<1, 512>>>();
    k_bn_stats<<<2048, 256>>>(pC);
    k_bn_final<<<1, 512>>>(gamma, beta);

    // split C with fused BN+LReLU -> fp16 h/l
    k_split<<<(elem4 + 255) / 256, 256>>>((const float4*)pC, pScale, pShift,
                                          (uint2*)pAh, (uint2*)pAl);

    // layer 1
    k_gemm<<<nblk, 256, SMEMSZ>>>(pAh, pAl, wch, nullptr, pB, pC, bc,
                                  nullptr, nullptr);
    k_scatter<<<(edge4 + 255) / 256, 256>>>(ei, pB, pC);
    k_bnzero<<<1, 512>>>();
    k_bn_stats<<<2048, 256>>>(pC);
    k_bn_final<<<1, 512>>>(gamma, beta);

    // fused tail
    k_out<<<(NN * 32 + 255) / 256, 256>>>(pC, out);
}

// round 9
// speedup vs baseline: 2.6652x; 1.3674x over previous
#include <cuda_runtime.h>
#include <cuda_fp16.h>
#include <cstdint>
#include <cstddef>

#define NN 100000
#define HH 512
#define EE 160000
#define BN_EPS 1e-5f
#define SLOPE 0.01f

// ---------------- scratch ----------------
__device__ float g_B[(size_t)NN * HH];
__device__ float g_C[(size_t)NN * HH];
__device__ __half g_Ah[(size_t)NN * HH];   // fp16 GEMM input
__device__ __half g_Bh[(size_t)NN * HH];   // fp16 GEMM1 output
__device__ float g_dinv[NN];
__device__ int   g_deg[NN];
__device__ float g_colsum[HH];
__device__ float g_colsq[HH];
__device__ float g_scale[HH];
__device__ float g_shift[HH];
__device__ float g_weff[HH + 1];
__device__ int   g_is64;

// transposed fp16 weights: T[n][k] = fp16(W[k][n])
__device__ __half g_w1h[HH * HH];
__device__ __half g_wch[HH * HH];

// ---------------- helpers ----------------
__device__ __forceinline__ uint32_t smem_u32(const void* p) {
    uint32_t a;
    asm("{ .reg .u64 t; cvta.to.shared.u64 t, %1; cvt.u32.u64 %0, t; }"
        : "=r"(a) : "l"(p));
    return a;
}
__device__ __forceinline__ void ldsm_x4(uint32_t* r, uint32_t addr) {
    asm volatile("ldmatrix.sync.aligned.m8n8.x4.shared.b16 {%0,%1,%2,%3}, [%4];"
                 : "=r"(r[0]), "=r"(r[1]), "=r"(r[2]), "=r"(r[3]) : "r"(addr));
}
__device__ __forceinline__ void mma_f16(float* d, const uint32_t* a,
                                        const uint32_t* b) {
    asm volatile(
        "mma.sync.aligned.m16n8k16.row.col.f32.f16.f16.f32 "
        "{%0,%1,%2,%3}, {%4,%5,%6,%7}, {%8,%9}, {%0,%1,%2,%3};"
        : "+f"(d[0]), "+f"(d[1]), "+f"(d[2]), "+f"(d[3])
        : "r"(a[0]), "r"(a[1]), "r"(a[2]), "r"(a[3]), "r"(b[0]), "r"(b[1]));
}
__device__ __forceinline__ void cp16(uint32_t dst, const void* src) {
    asm volatile("cp.async.cg.shared.global [%0], [%1], 16;"
                 :: "r"(dst), "l"(src));
}
__device__ __forceinline__ float lrelu1(float x) {
    return x >= 0.f ? x : SLOPE * x;
}
__device__ __forceinline__ float4 xform(float4 v, int col,
                                        const float* __restrict__ scale,
                                        const float* __restrict__ shift) {
    float4 s = __ldg((const float4*)(scale + col));
    float4 t = __ldg((const float4*)(shift + col));
    v.x = lrelu1(fmaf(s.x, v.x, t.x));
    v.y = lrelu1(fmaf(s.y, v.y, t.y));
    v.z = lrelu1(fmaf(s.z, v.z, t.z));
    v.w = lrelu1(fmaf(s.w, v.w, t.w));
    return v;
}
__device__ __forceinline__ uint32_t packh(__half a, __half b) {
    return ((uint32_t)__half_as_ushort(a)) |
           ((uint32_t)__half_as_ushort(b) << 16);
}

// ---------------- setup ----------------
__global__ void k_prep(const int* __restrict__ ei) {
    int i = blockIdx.x * blockDim.x + threadIdx.x;
    if (i == 0)
        g_is64 = ((ei[1] | ei[3] | ei[5] | ei[7] | ei[9]) == 0) ? 1 : 0;
    if (i < NN) g_deg[i] = 0;
}
__global__ void k_deg(const int* __restrict__ ei) {
    int e = blockIdx.x * blockDim.x + threadIdx.x;
    if (e >= EE) return;
    int is64 = g_is64;
    int dst = is64 ? ei[2 * EE + 2 * e] : ei[EE + e];
    atomicAdd(&g_deg[dst], 1);
}
__global__ void k_dinv() {
    int i = blockIdx.x * blockDim.x + threadIdx.x;
    if (i < NN) g_dinv[i] = rsqrtf((float)g_deg[i] + 1.0f);
}
__global__ void k_conv_w(const float* __restrict__ W, __half* __restrict__ Th) {
    int k = blockIdx.x;
    for (int n = threadIdx.x; n < HH; n += blockDim.x)
        Th[(size_t)n * HH + k] = __float2half_rn(W[(size_t)k * HH + n]);
}

// fp32 -> fp16, optional fused BN+LReLU
__global__ void k_split(const float4* __restrict__ in,
                        const float* __restrict__ scale,
                        const float* __restrict__ shift,
                        uint2* __restrict__ outh) {
    int i = blockIdx.x * blockDim.x + threadIdx.x;
    if (i >= NN * (HH / 4)) return;
    float4 v = in[i];
    if (scale) {
        int c = (i & (HH / 4 - 1)) << 2;
        v = xform(v, c, scale, shift);
    }
    uint2 hp;
    hp.x = packh(__float2half_rn(v.x), __float2half_rn(v.y));
    hp.y = packh(__float2half_rn(v.z), __float2half_rn(v.w));
    outh[i] = hp;
}

// ---------------- GEMM: plain fp16 HMMA, cp.async 2-stage pipeline --------
#define BM 128
#define BNT 128
#define BK 32
#define NCHUNK (HH / BK)   // 16
#define PADK 40            // 80B row stride: conflict-free ldmatrix
#define ROWB (PADK * 2)
#define OFF_A 0
#define OFF_B 10240
#define STG   20480
#define SMEMSZ (2 * STG)   // 40960

__global__ __launch_bounds__(256, 2)
void k_gemm(const __half* __restrict__ Ah,
            const __half* __restrict__ Wh,
            const float* __restrict__ bias,
            float* __restrict__ Cf,            // fp32 out (or null)
            float* __restrict__ C2f,           // fp32 agg out (or null)
            const float* __restrict__ bc,      // agg bias
            __half* __restrict__ Ch) {         // fp16 out (or null)
    extern __shared__ char smem[];
    const uint32_t sbase = smem_u32(smem);
    const int tid = threadIdx.x;
    const int wid = tid >> 5;
    const int lane = tid & 31;
    const int bm = (blockIdx.x >> 2) * BM;
    const int bn = (blockIdx.x & 3) * BNT;
    const int wm = (wid & 1) * 64;
    const int wn = (wid >> 1) * 32;

    const char* pAh = (const char*)Ah;
    const char* pWh = (const char*)Wh;

    float acc[4][4][4];
#pragma unroll
    for (int i = 0; i < 4; i++)
#pragma unroll
        for (int j = 0; j < 4; j++)
#pragma unroll
            for (int f = 0; f < 4; f++) acc[i][j][f] = 0.f;

#define ISSUE(s)                                                              \
    do {                                                                      \
        const uint32_t stu = sbase + ((s) & 1) * STG;                         \
        const size_t kb = (size_t)(s) * 64;                                   \
        _Pragma("unroll")                                                     \
        for (int i = 0; i < 2; i++) {                                         \
            int idx = tid + i * 256;                                          \
            int r = idx >> 2, c16 = (idx & 3) << 4;                           \
            int grow = bm + r;                                                \
            if (grow < NN)                                                    \
                cp16(stu + OFF_A + r * ROWB + c16,                            \
                     pAh + (size_t)grow * (HH * 2) + kb + c16);               \
            cp16(stu + OFF_B + r * ROWB + c16,                                \
                 pWh + (size_t)(bn + r) * (HH * 2) + kb + c16);               \
        }                                                                     \
    } while (0)

    ISSUE(0);
    asm volatile("cp.async.commit_group;" ::: "memory");

    for (int s = 0; s < NCHUNK; s++) {
        if (s > 0) __syncthreads();
        if (s + 1 < NCHUNK) ISSUE(s + 1);
        asm volatile("cp.async.commit_group;" ::: "memory");
        asm volatile("cp.async.wait_group 1;" ::: "memory");
        __syncthreads();

        const uint32_t stu = sbase + (s & 1) * STG;
        const uint32_t lrow = (lane & 15);
        const uint32_t lk = (lane >> 4) * 8;
#pragma unroll
        for (int ks = 0; ks < 2; ks++) {
            const int k0 = ks * 16;
            uint32_t bh[4][2];
#pragma unroll
            for (int p = 0; p < 2; p++) {
                uint32_t off = ((wn + p * 16 + lrow) * PADK + k0 + lk) * 2;
                uint32_t t[4];
                ldsm_x4(t, stu + OFF_B + off);
                bh[p * 2 + 0][0] = t[0]; bh[p * 2 + 0][1] = t[2];
                bh[p * 2 + 1][0] = t[1]; bh[p * 2 + 1][1] = t[3];
            }
#pragma unroll
            for (int mi = 0; mi < 4; mi++) {
                uint32_t off = ((wm + mi * 16 + lrow) * PADK + k0 + lk) * 2;
                uint32_t ah[4];
                ldsm_x4(ah, stu + OFF_A + off);
#pragma unroll
                for (int ni = 0; ni < 4; ni++)
                    mma_f16(acc[mi][ni], ah, bh[ni]);
            }
        }
    }

    // ---- epilogue ----
#pragma unroll
    for (int mi = 0; mi < 4; mi++) {
        int row0 = bm + wm + mi * 16 + (lane >> 2);
        int row1 = row0 + 8;
        float d0 = 0.f, d1 = 0.f;
        if (C2f) {
            if (row0 < NN) { d0 = g_dinv[row0]; d0 *= d0; }
            if (row1 < NN) { d1 = g_dinv[row1]; d1 *= d1; }
        }
#pragma unroll
        for (int ni = 0; ni < 4; ni++) {
            int col = bn + wn + ni * 8 + (lane & 3) * 2;
            float b0 = bias ? bias[col] : 0.f;
            float b1 = bias ? bias[col + 1] : 0.f;
            float v00 = acc[mi][ni][0] + b0, v01 = acc[mi][ni][1] + b1;
            float v10 = acc[mi][ni][2] + b0, v11 = acc[mi][ni][3] + b1;
            if (Ch) {
                if (row0 < NN)
                    *(uint32_t*)(Ch + (size_t)row0 * HH + col) =
                        packh(__float2half_rn(v00), __float2half_rn(v01));
                if (row1 < NN)
                    *(uint32_t*)(Ch + (size_t)row1 * HH + col) =
                        packh(__float2half_rn(v10), __float2half_rn(v11));
            } else {
                if (row0 < NN)
                    *(float2*)(Cf + (size_t)row0 * HH + col) =
                        make_float2(v00, v01);
                if (row1 < NN)
                    *(float2*)(Cf + (size_t)row1 * HH + col) =
                        make_float2(v10, v11);
                if (C2f) {
                    float c0 = bc[col], c1 = bc[col + 1];
                    if (row0 < NN)
                        *(float2*)(C2f + (size_t)row0 * HH + col) =
                            make_float2(fmaf(d0, v00, c0), fmaf(d0, v01, c1));
                    if (row1 < NN)
                        *(float2*)(C2f + (size_t)row1 * HH + col) =
                            make_float2(fmaf(d1, v10, c0), fmaf(d1, v11, c1));
                }
            }
        }
    }
}

// ---------------- scatter ----------------
__global__ void k_scatter(const int* __restrict__ ei, const float* __restrict__ B,
                          float* __restrict__ A) {
    int g = blockIdx.x * blockDim.x + threadIdx.x;
    if (g >= EE * (HH / 4)) return;
    int e = g >> 7;
    int j = (g & 127) << 2;
    int is64 = g_is64;
    int src = is64 ? ei[2 * e] : ei[e];
    int dst = is64 ? ei[2 * EE + 2 * e] : ei[EE + e];
    float w = g_dinv[src] * g_dinv[dst];
    float4 v = *(const float4*)(B + (size_t)src * HH + j);
    float* out = A + (size_t)dst * HH + j;
    asm volatile("red.global.add.v4.f32 [%0], {%1, %2, %3, %4};"
                 :: "l"(out), "f"(w * v.x), "f"(w * v.y), "f"(w * v.z),
                    "f"(w * v.w)
                 : "memory");
}

// ---------------- batchnorm stats ----------------
__global__ void k_bnzero() {
    int i = threadIdx.x;
    g_colsum[i] = 0.f;
    g_colsq[i] = 0.f;
}
__global__ void k_bn_stats(const float* __restrict__ A) {
    int c = threadIdx.x;
    float s0 = 0.f, q0 = 0.f, s1 = 0.f, q1 = 0.f;
    for (int r = blockIdx.x; r < NN; r += gridDim.x) {
        const float* row = A + (size_t)r * HH;
        float v0 = row[c];
        float v1 = row[c + 256];
        s0 += v0; q0 += v0 * v0;
        s1 += v1; q1 += v1 * v1;
    }
    atomicAdd(&g_colsum[c], s0);
    atomicAdd(&g_colsq[c], q0);
    atomicAdd(&g_colsum[c + 256], s1);
    atomicAdd(&g_colsq[c + 256], q1);
}
__global__ void k_bn_final(const float* __restrict__ gamma,
                           const float* __restrict__ beta) {
    int c = threadIdx.x;
    float inv_n = 1.0f / (float)NN;
    float mean = g_colsum[c] * inv_n;
    float var = g_colsq[c] * inv_n - mean * mean;
    float sc = gamma[c] * rsqrtf(var + BN_EPS);
    g_scale[c] = sc;
    g_shift[c] = beta[c] - mean * sc;
}

// ---------------- fused tail ----------------
__global__ void k_weff(const float* __restrict__ W2, const float* __restrict__ b2,
                       const float* __restrict__ WO, const float* __restrict__ bO) {
    int b = blockIdx.x;
    const float* rowp = (b < HH) ? (W2 + (size_t)b * HH) : b2;
    float s = 0.f;
    for (int j = threadIdx.x; j < HH; j += 256) s += rowp[j] * WO[j];
#pragma unroll
    for (int o = 16; o; o >>= 1) s += __shfl_xor_sync(0xffffffffu, s, o);
    __shared__ float red[8];
    if ((threadIdx.x & 31) == 0) red[threadIdx.x >> 5] = s;
    __syncthreads();
    if (threadIdx.x == 0) {
        float t = 0.f;
        for (int i = 0; i < 8; i++) t += red[i];
        g_weff[b] = (b < HH) ? t : (t + bO[0]);
    }
}

__global__ void k_out(const float* __restrict__ A, float* __restrict__ out) {
    int w = (blockIdx.x * blockDim.x + threadIdx.x) >> 5;
    int lane = threadIdx.x & 31;
    if (w >= NN) return;
    const float4* row = (const float4*)(A + (size_t)w * HH);
    const float4* wf = (const float4*)g_weff;
    const float4* sc4 = (const float4*)g_scale;
    const float4* sh4 = (const float4*)g_shift;
    float s = 0.f;
#pragma unroll
    for (int i = 0; i < 4; i++) {
        int idx = lane + 32 * i;
        float4 a = row[idx];
        float4 b = wf[idx];
        float4 sc = sc4[idx];
        float4 sh = sh4[idx];
        a.x = lrelu1(fmaf(sc.x, a.x, sh.x));
        a.y = lrelu1(fmaf(sc.y, a.y, sh.y));
        a.z = lrelu1(fmaf(sc.z, a.z, sh.z));
        a.w = lrelu1(fmaf(sc.w, a.w, sh.w));
        s += a.x * b.x + a.y * b.y + a.z * b.z + a.w * b.w;
    }
#pragma unroll
    for (int o = 16; o; o >>= 1) s += __shfl_xor_sync(0xffffffffu, s, o);
    if (lane == 0) {
        float t = s + g_weff[HH];
        out[w] = 1.0f / (1.0f + expf(-t));
    }
}

// ---------------- launcher ----------------
extern "C" void kernel_launch(void* const* d_in, const int* in_sizes, int n_in,
                              void* d_out, int out_size) {
    const float* x     = (const float*)d_in[0];
    const int*   ei    = (const int*)d_in[1];
    const float* W1    = (const float*)d_in[2];
    const float* b1    = (const float*)d_in[3];
    const float* Wc    = (const float*)d_in[4];
    const float* bc    = (const float*)d_in[5];
    const float* gamma = (const float*)d_in[6];
    const float* beta  = (const float*)d_in[7];
    const float* W2    = (const float*)d_in[8];
    const float* b2    = (const float*)d_in[9];
    const float* WO    = (const float*)d_in[10];
    const float* bO    = (const float*)d_in[11];
    float* out = (float*)d_out;

    float *pB, *pC, *pScale, *pShift;
    cudaGetSymbolAddress((void**)&pB, g_B);
    cudaGetSymbolAddress((void**)&pC, g_C);
    cudaGetSymbolAddress((void**)&pScale, g_scale);
    cudaGetSymbolAddress((void**)&pShift, g_shift);
    __half *pAh, *pBh, *w1h, *wch;
    cudaGetSymbolAddress((void**)&pAh, g_Ah);
    cudaGetSymbolAddress((void**)&pBh, g_Bh);
    cudaGetSymbolAddress((void**)&w1h, g_w1h);
    cudaGetSymbolAddress((void**)&wch, g_wch);

    cudaFuncSetAttribute(k_gemm, cudaFuncAttributeMaxDynamicSharedMemorySize,
                         SMEMSZ);

    k_prep<<<(NN + 255) / 256, 256>>>(ei);
    k_deg<<<(EE + 255) / 256, 256>>>(ei);
    k_dinv<<<(NN + 255) / 256, 256>>>();
    k_conv_w<<<HH, 256>>>(W1, w1h);
    k_conv_w<<<HH, 256>>>(Wc, wch);
    k_weff<<<HH + 1, 256>>>(W2, b2, WO, bO);

    const int nblk = ((NN + BM - 1) / BM) * 4;   // 3128
    const int elem4 = NN * (HH / 4);
    const int edge4 = EE * (HH / 4);

    // x -> fp16
    k_split<<<(elem4 + 255) / 256, 256>>>((const float4*)x, nullptr, nullptr,
                                          (uint2*)pAh);

    // GEMM1: h = x@W1 + b1, fp16 output
    k_gemm<<<nblk, 256, SMEMSZ>>>(pAh, w1h, b1, nullptr, nullptr, nullptr,
                                  pBh);

    // layer 0: B = h@Wc (fp32) + C = agg-init; scatter; stats
    k_gemm<<<nblk, 256, SMEMSZ>>>(pBh, wch, nullptr, pB, pC, bc, nullptr);
    k_scatter<<<(edge4 + 255) / 256, 256>>>(ei, pB, pC);
    k_bnzero<<<1, 512>>>();
    k_bn_stats<<<2048, 256>>>(pC);
    k_bn_final<<<1, 512>>>(gamma, beta);

    // C -> fp16 with fused BN+LReLU
    k_split<<<(elem4 + 255) / 256, 256>>>((const float4*)pC, pScale, pShift,
                                          (uint2*)pAh);

    // layer 1
    k_gemm<<<nblk, 256, SMEMSZ>>>(pAh, wch, nullptr, pB, pC, bc, nullptr);
    k_scatter<<<(edge4 + 255) / 256, 256>>>(ei, pB, pC);
    k_bnzero<<<1, 512>>>();
    k_bn_stats<<<2048, 256>>>(pC);
    k_bn_final<<<1, 512>>>(gamma, beta);

    // fused tail
    k_out<<<(NN * 32 + 255) / 256, 256>>>(pC, out);
}